// round 6
// baseline (speedup 1.0000x reference)
#include <cuda_runtime.h>
#include <cstddef>

// Problem constants (fixed by the reference: N=1024, D=16, E=16384)
#define NNODES 1024
#define D_DIM  16
#define NM     16384          // N * D
#define EMAX   16384

// ---------------- scratch (device globals: allocation-free) ----------------
__device__ float g_triu[(size_t)EMAX * 256];    // 16.8 MB: -dr*dc*(A^T B), final values
__device__ float g_diag[(size_t)NNODES * 256];  //  1.0 MB: dinv^2-scaled Gram sums

// Side stream + events for the memset/inject pipeline under graph capture.
// Created once at static-init time (host/driver objects only).
namespace {
struct StreamPack {
    cudaStream_t s2;
    cudaEvent_t  fork_ev, m_ev[4], done_ev;
    StreamPack() {
        cudaStreamCreateWithFlags(&s2, cudaStreamNonBlocking);
        cudaEventCreateWithFlags(&fork_ev, cudaEventDisableTiming);
        for (int i = 0; i < 4; ++i)
            cudaEventCreateWithFlags(&m_ev[i], cudaEventDisableTiming);
        cudaEventCreateWithFlags(&done_ev, cudaEventDisableTiming);
    }
};
StreamPack g_sp;
}

// Inline edge_index dtype probe (deterministic single word):
// int32 layout (2,32768): word 32769 = edge_index[1][1] = col[1] >= 1 (r < c).
// int64 LE layout: word 32769 = high half of edge_index[0][16384] < 1024 -> 0.
__device__ __forceinline__ int idx_stride(const int* eidx32) {
    return (__ldg(&eidx32[32769]) != 0) ? 1 : 2;
}

// Pass 1: 4 edges per CTA, 64 threads per edge, 4 outputs per thread.
//   g_triu[e]  = -dinv[r]*dinv[c] * (A^T B)   (final scaled value)
//   g_diag[r] += dinv[r]^2 * (A^T A)          (atomic, 1 MB L2-resident scratch)
//   g_diag[c] += dinv[c]^2 * (B^T B)
__global__ void __launch_bounds__(256) edge_compute_kernel(
        const float* __restrict__ degrees,
        const float* __restrict__ maps,
        const int*   __restrict__ eidx32,
        int E) {
    __shared__ float Asm[4][256];
    __shared__ float Bsm[4][256];

    const int tid = threadIdx.x;
    const int g   = tid >> 6;
    const int lt  = tid & 63;
    const int e   = blockIdx.x * 4 + g;

    const int stride = idx_stride(eidx32);
    const int r = eidx32[(size_t)e * stride];
    const int c = eidx32[(size_t)(2 * E + e) * stride];

    #pragma unroll
    for (int i = lt; i < 256; i += 64) {
        Asm[g][i] = maps[(size_t)e * 256 + i];
        Bsm[g][i] = maps[((size_t)e + E) * 256 + i];
    }
    __syncthreads();

    const int j0 = lt >> 3;            // 0..7   (rows j0, j0+8)
    const int k0 = lt & 7;             // 0..7   (cols k0, k0+8)

    float t00 = 0.f, t01 = 0.f, t10 = 0.f, t11 = 0.f;
    float p00 = 0.f, p01 = 0.f, p10 = 0.f, p11 = 0.f;   // A^T A
    float q00 = 0.f, q01 = 0.f, q10 = 0.f, q11 = 0.f;   // B^T B

    #pragma unroll
    for (int i = 0; i < 16; ++i) {
        const float aj0 = Asm[g][i * 16 + j0];
        const float aj1 = Asm[g][i * 16 + j0 + 8];
        const float ak0 = Asm[g][i * 16 + k0];
        const float ak1 = Asm[g][i * 16 + k0 + 8];
        const float bj0 = Bsm[g][i * 16 + j0];
        const float bj1 = Bsm[g][i * 16 + j0 + 8];
        const float bk0 = Bsm[g][i * 16 + k0];
        const float bk1 = Bsm[g][i * 16 + k0 + 8];
        t00 += aj0 * bk0;  t01 += aj0 * bk1;  t10 += aj1 * bk0;  t11 += aj1 * bk1;
        p00 += aj0 * ak0;  p01 += aj0 * ak1;  p10 += aj1 * ak0;  p11 += aj1 * ak1;
        q00 += bj0 * bk0;  q01 += bj0 * bk1;  q10 += bj1 * bk0;  q11 += bj1 * bk1;
    }

    const float dr = rsqrtf(degrees[r] * (float)D_DIM + 1.0f);
    const float dc = rsqrtf(degrees[c] * (float)D_DIM + 1.0f);
    const float s  = -(dr * dc);
    const float sr = dr * dr;
    const float sc = dc * dc;

    float* tr = &g_triu[(size_t)e * 256];
    tr[j0 * 16 + k0]            = s * t00;
    tr[j0 * 16 + k0 + 8]        = s * t01;
    tr[(j0 + 8) * 16 + k0]      = s * t10;
    tr[(j0 + 8) * 16 + k0 + 8]  = s * t11;

    float* dgr = &g_diag[(size_t)r * 256];
    atomicAdd(&dgr[j0 * 16 + k0],           sr * p00);
    atomicAdd(&dgr[j0 * 16 + k0 + 8],       sr * p01);
    atomicAdd(&dgr[(j0 + 8) * 16 + k0],     sr * p10);
    atomicAdd(&dgr[(j0 + 8) * 16 + k0 + 8], sr * p11);

    float* dgc = &g_diag[(size_t)c * 256];
    atomicAdd(&dgc[j0 * 16 + k0],           sc * q00);
    atomicAdd(&dgc[j0 * 16 + k0 + 8],       sc * q01);
    atomicAdd(&dgc[(j0 + 8) * 16 + k0],     sc * q10);
    atomicAdd(&dgc[(j0 + 8) * 16 + k0 + 8], sc * q11);
}

// Range-restricted edge inject: writes only blocks whose TARGET row-node is
// in [lo, hi). 4 edges per CTA, 64 threads per edge, float4 everywhere.
__global__ void __launch_bounds__(256) inject_edges_kernel(
        const int* __restrict__ eidx32,
        float*     __restrict__ out,
        int E, int lo, int hi) {
    __shared__ float Ts[4][16][17];

    const int tid = threadIdx.x;
    const int g   = tid >> 6;
    const int lt  = tid & 63;
    const int e   = blockIdx.x * 4 + g;

    const int stride = idx_stride(eidx32);
    const int r = eidx32[(size_t)e * stride];
    const int c = eidx32[(size_t)(2 * E + e) * stride];

    const bool want_triu = (r >= lo) & (r < hi);
    const bool want_tril = (c >= lo) & (c < hi);

    const int j = lt >> 2;     // row 0..15
    const int q = lt & 3;      // float4 column group 0..3

    float4 v = make_float4(0.f, 0.f, 0.f, 0.f);
    if (want_triu | want_tril)
        v = *(const float4*)&g_triu[(size_t)e * 256 + j * 16 + q * 4];

    if (want_triu)
        *(float4*)&out[(size_t)(r * 16 + j) * NM + c * 16 + q * 4] = v;

    // Transposed store into smem: Ts[k][j] = t[j][k]
    Ts[g][q * 4 + 0][j] = v.x;
    Ts[g][q * 4 + 1][j] = v.y;
    Ts[g][q * 4 + 2][j] = v.z;
    Ts[g][q * 4 + 3][j] = v.w;
    __syncthreads();

    if (want_tril) {
        // tril[j][k] = t[k][j] = Ts[j][k]
        float4 w;
        w.x = Ts[g][j][q * 4 + 0];
        w.y = Ts[g][j][q * 4 + 1];
        w.z = Ts[g][j][q * 4 + 2];
        w.w = Ts[g][j][q * 4 + 3];
        *(float4*)&out[(size_t)(c * 16 + j) * NM + r * 16 + q * 4] = w;
    }
}

// Diag inject for nodes [lo, lo + 4*gridDim.x): 4 nodes/CTA, float4.
__global__ void __launch_bounds__(256) inject_diag_kernel(
        float* __restrict__ out, int lo) {
    const int tid  = threadIdx.x;
    const int node = lo + blockIdx.x * 4 + (tid >> 6);
    const int lt   = tid & 63;
    const int j    = lt >> 2;
    const int q    = lt & 3;

    const float4 v = *(const float4*)&g_diag[(size_t)node * 256 + j * 16 + q * 4];
    *(float4*)&out[(size_t)(node * 16 + j) * NM + node * 16 + q * 4] = v;
}

extern "C" void kernel_launch(void* const* d_in, const int* in_sizes, int n_in,
                              void* d_out, int out_size) {
    // Inputs (metadata order): adj_mat [N*N f32], degrees [N f32],
    // maps [2E*16*16 f32], edge_index [2*2E int]
    const float* degrees = (const float*)d_in[1];
    const float* maps    = (const float*)d_in[2];
    const int*   eidx32  = (const int*)d_in[3];
    float*       out     = (float*)d_out;

    const int E = in_sizes[2] / (2 * 256);   // maps has 2E blocks of 256 floats

    void* diag_ptr = nullptr;
    cudaGetSymbolAddress(&diag_ptr, g_diag);

    const size_t total_bytes = (size_t)out_size * sizeof(float);
    const size_t qbytes      = total_bytes / 4;       // one quarter = nodes [i*256,(i+1)*256)

    // Fork: side stream runs pass1 (scratch only) while quarter-memsets stream.
    cudaEventRecord(g_sp.fork_ev, 0);
    cudaStreamWaitEvent(g_sp.s2, g_sp.fork_ev, 0);

    cudaMemsetAsync(diag_ptr, 0, (size_t)NNODES * 256 * sizeof(float), g_sp.s2);
    edge_compute_kernel<<<E / 4, 256, 0, g_sp.s2>>>(degrees, maps, eidx32, E);

    // Capture stream: four 256 MB zero fills, event after each.
    for (int i = 0; i < 4; ++i) {
        cudaMemsetAsync((char*)d_out + (size_t)i * qbytes, 0, qbytes, 0);
        cudaEventRecord(g_sp.m_ev[i], 0);
    }

    // Side stream: inject quarter i as soon as its memset is done, pipelined
    // against the remaining memsets. (s2 order already serializes after pass1.)
    for (int i = 0; i < 4; ++i) {
        cudaStreamWaitEvent(g_sp.s2, g_sp.m_ev[i], 0);
        inject_edges_kernel<<<E / 4, 256, 0, g_sp.s2>>>(eidx32, out, E,
                                                        i * 256, (i + 1) * 256);
        inject_diag_kernel<<<64, 256, 0, g_sp.s2>>>(out, i * 256);
    }

    cudaEventRecord(g_sp.done_ev, g_sp.s2);
    cudaStreamWaitEvent(0, g_sp.done_ev, 0);
}

// round 7
// speedup vs baseline: 1.1604x; 1.1604x over previous
#include <cuda_runtime.h>
#include <cstddef>

// Problem constants (fixed by the reference: N=1024, D=16, E=16384)
#define NNODES 1024
#define D_DIM  16
#define NM     16384          // N * D
#define EMAX   16384

// ---------------- scratch (device globals: allocation-free) ----------------
__device__ float g_diag[(size_t)NNODES * 256];  // 1.0 MB: dinv^2-scaled Gram sums

// Inline edge_index dtype probe (deterministic single word):
// int32 layout (2,32768): word 32769 = edge_index[1][1] = col[1] >= 1 (r < c).
// int64 LE layout: word 32769 = high half of edge_index[0][16384] < 1024 -> 0.
__device__ __forceinline__ int idx_stride(const int* eidx32) {
    return (__ldg(&eidx32[32769]) != 0) ? 1 : 2;
}

// Fused pass (after the memset): 4 edges per CTA, 64 threads per edge.
// Computes T = A^T B, G1 = A^T A, G2 = B^T B with 4 outputs/thread
// (8 LDS feed 12 FMAs per i-step), then:
//   - stages -dr*dc*T in smem and emits float4-coalesced direct stores of
//     the triu block at (r,c) and its transpose at (c,r) into `out`
//   - atomically accumulates scaled G1/G2 into the 1 MB L2-resident g_diag
__global__ void __launch_bounds__(256) edge_fused_kernel(
        const float* __restrict__ degrees,
        const float* __restrict__ maps,
        const int*   __restrict__ eidx32,
        float*       __restrict__ out,
        int E) {
    __shared__ float Asm[4][256];
    __shared__ float Bsm[4][256];
    __shared__ float Tsm[4][16][17];   // scaled T, padded against bank conflicts

    const int tid = threadIdx.x;
    const int g   = tid >> 6;          // edge slot 0..3
    const int lt  = tid & 63;
    const int e   = blockIdx.x * 4 + g;

    const int stride = idx_stride(eidx32);
    const int r = eidx32[(size_t)e * stride];
    const int c = eidx32[(size_t)(2 * E + e) * stride];

    #pragma unroll
    for (int i = lt; i < 256; i += 64) {
        Asm[g][i] = maps[(size_t)e * 256 + i];
        Bsm[g][i] = maps[((size_t)e + E) * 256 + i];
    }
    __syncthreads();

    const int j0 = lt >> 3;            // 0..7   (rows j0, j0+8)
    const int k0 = lt & 7;             // 0..7   (cols k0, k0+8)

    float t00 = 0.f, t01 = 0.f, t10 = 0.f, t11 = 0.f;
    float p00 = 0.f, p01 = 0.f, p10 = 0.f, p11 = 0.f;   // A^T A
    float q00 = 0.f, q01 = 0.f, q10 = 0.f, q11 = 0.f;   // B^T B

    #pragma unroll
    for (int i = 0; i < 16; ++i) {
        const float aj0 = Asm[g][i * 16 + j0];
        const float aj1 = Asm[g][i * 16 + j0 + 8];
        const float ak0 = Asm[g][i * 16 + k0];
        const float ak1 = Asm[g][i * 16 + k0 + 8];
        const float bj0 = Bsm[g][i * 16 + j0];
        const float bj1 = Bsm[g][i * 16 + j0 + 8];
        const float bk0 = Bsm[g][i * 16 + k0];
        const float bk1 = Bsm[g][i * 16 + k0 + 8];
        t00 += aj0 * bk0;  t01 += aj0 * bk1;  t10 += aj1 * bk0;  t11 += aj1 * bk1;
        p00 += aj0 * ak0;  p01 += aj0 * ak1;  p10 += aj1 * ak0;  p11 += aj1 * ak1;
        q00 += bj0 * bk0;  q01 += bj0 * bk1;  q10 += bj1 * bk0;  q11 += bj1 * bk1;
    }

    const float dr = rsqrtf(degrees[r] * (float)D_DIM + 1.0f);
    const float dc = rsqrtf(degrees[c] * (float)D_DIM + 1.0f);
    const float s  = -(dr * dc);
    const float sr = dr * dr;
    const float sc = dc * dc;

    // Diagonal Gram contributions into the small L2-resident scratch
    float* dgr = &g_diag[(size_t)r * 256];
    atomicAdd(&dgr[j0 * 16 + k0],           sr * p00);
    atomicAdd(&dgr[j0 * 16 + k0 + 8],       sr * p01);
    atomicAdd(&dgr[(j0 + 8) * 16 + k0],     sr * p10);
    atomicAdd(&dgr[(j0 + 8) * 16 + k0 + 8], sr * p11);

    float* dgc = &g_diag[(size_t)c * 256];
    atomicAdd(&dgc[j0 * 16 + k0],           sc * q00);
    atomicAdd(&dgc[j0 * 16 + k0 + 8],       sc * q01);
    atomicAdd(&dgc[(j0 + 8) * 16 + k0],     sc * q10);
    atomicAdd(&dgc[(j0 + 8) * 16 + k0 + 8], sc * q11);

    // Stage the scaled triu block in smem
    Tsm[g][j0][k0]          = s * t00;
    Tsm[g][j0][k0 + 8]      = s * t01;
    Tsm[g][j0 + 8][k0]      = s * t10;
    Tsm[g][j0 + 8][k0 + 8]  = s * t11;
    __syncthreads();

    // Re-map 64 threads to 16 rows x 4 float4 groups for coalesced stores
    const int j = lt >> 2;     // row 0..15
    const int q = lt & 3;      // float4 column group 0..3

    float4 v;                  // triu block, row j
    v.x = Tsm[g][j][q * 4 + 0];
    v.y = Tsm[g][j][q * 4 + 1];
    v.z = Tsm[g][j][q * 4 + 2];
    v.w = Tsm[g][j][q * 4 + 3];
    *(float4*)&out[(size_t)(r * 16 + j) * NM + c * 16 + q * 4] = v;

    float4 w;                  // tril block = transpose, row j
    w.x = Tsm[g][q * 4 + 0][j];
    w.y = Tsm[g][q * 4 + 1][j];
    w.z = Tsm[g][q * 4 + 2][j];
    w.w = Tsm[g][q * 4 + 3][j];
    *(float4*)&out[(size_t)(c * 16 + j) * NM + r * 16 + q * 4] = w;
}

// Diag flush: 4 nodes per CTA, float4 copies of the accumulated Gram blocks.
__global__ void __launch_bounds__(256) inject_diag_kernel(float* __restrict__ out) {
    const int tid  = threadIdx.x;
    const int node = blockIdx.x * 4 + (tid >> 6);
    const int lt   = tid & 63;
    const int j    = lt >> 2;
    const int q    = lt & 3;

    const float4 v = *(const float4*)&g_diag[(size_t)node * 256 + j * 16 + q * 4];
    *(float4*)&out[(size_t)(node * 16 + j) * NM + node * 16 + q * 4] = v;
}

extern "C" void kernel_launch(void* const* d_in, const int* in_sizes, int n_in,
                              void* d_out, int out_size) {
    // Inputs (metadata order): adj_mat [N*N f32], degrees [N f32],
    // maps [2E*16*16 f32], edge_index [2*2E int]
    const float* degrees = (const float*)d_in[1];
    const float* maps    = (const float*)d_in[2];
    const int*   eidx32  = (const int*)d_in[3];
    float*       out     = (float*)d_out;

    const int E = in_sizes[2] / (2 * 256);   // maps has 2E blocks of 256 floats

    void* diag_ptr = nullptr;
    cudaGetSymbolAddress(&diag_ptr, g_diag);

    // 1) Zero the 1 MB diag scratch (trivial) + the 1.07 GB output (dominant,
    //    kept pure and serial: measured 7.2 TB/s, degrades under any overlap)
    cudaMemsetAsync(diag_ptr, 0, (size_t)NNODES * 256 * sizeof(float), 0);
    cudaMemsetAsync(d_out, 0, (size_t)out_size * sizeof(float), 0);

    // 2) Fused: compute + direct triu/tril stores + diag atomics
    edge_fused_kernel<<<E / 4, 256>>>(degrees, maps, eidx32, out, E);

    // 3) Flush the accumulated diagonal blocks
    inject_diag_kernel<<<NNODES / 4, 256>>>(out);
}

// round 8
// speedup vs baseline: 1.1629x; 1.0022x over previous
#include <cuda_runtime.h>
#include <cstddef>

// Problem constants (fixed by the reference: N=1024, D=16, E=16384)
#define NNODES 1024
#define D_DIM  16
#define NM     16384          // N * D

// Inline edge_index dtype probe (deterministic single word):
// int32 layout (2,32768): word 32769 = edge_index[1][1] = col[1] >= 1 (r < c).
// int64 LE layout: word 32769 = high half of edge_index[0][16384] < 1024 -> 0.
__device__ __forceinline__ int idx_stride(const int* eidx32) {
    return (__ldg(&eidx32[32769]) != 0) ? 1 : 2;
}

// Fused pass (after the memset): 4 edges per CTA, 64 threads per edge.
// Computes T = A^T B, G1 = A^T A, G2 = B^T B with 4 outputs/thread
// (8 LDS feed 12 FMAs per i-step), then:
//   - stages -dr*dc*T in smem and emits float4-coalesced direct stores of
//     the triu block at (r,c) and its transpose at (c,r) into `out`
//   - atomically accumulates scaled G1/G2 straight into out's diagonal
//     blocks (memset provides the zero initial value; same L2 atomic cost
//     as a scratch buffer, but no flush kernel and no scratch memset)
__global__ void __launch_bounds__(256) edge_fused_kernel(
        const float* __restrict__ degrees,
        const float* __restrict__ maps,
        const int*   __restrict__ eidx32,
        float*       __restrict__ out,
        int E) {
    __shared__ float Asm[4][256];
    __shared__ float Bsm[4][256];
    __shared__ float Tsm[4][16][17];   // scaled T, padded against bank conflicts

    const int tid = threadIdx.x;
    const int g   = tid >> 6;          // edge slot 0..3
    const int lt  = tid & 63;
    const int e   = blockIdx.x * 4 + g;

    const int stride = idx_stride(eidx32);
    const int r = eidx32[(size_t)e * stride];
    const int c = eidx32[(size_t)(2 * E + e) * stride];

    #pragma unroll
    for (int i = lt; i < 256; i += 64) {
        Asm[g][i] = maps[(size_t)e * 256 + i];
        Bsm[g][i] = maps[((size_t)e + E) * 256 + i];
    }
    __syncthreads();

    const int j0 = lt >> 3;            // 0..7   (rows j0, j0+8)
    const int k0 = lt & 7;             // 0..7   (cols k0, k0+8)

    float t00 = 0.f, t01 = 0.f, t10 = 0.f, t11 = 0.f;
    float p00 = 0.f, p01 = 0.f, p10 = 0.f, p11 = 0.f;   // A^T A
    float q00 = 0.f, q01 = 0.f, q10 = 0.f, q11 = 0.f;   // B^T B

    #pragma unroll
    for (int i = 0; i < 16; ++i) {
        const float aj0 = Asm[g][i * 16 + j0];
        const float aj1 = Asm[g][i * 16 + j0 + 8];
        const float ak0 = Asm[g][i * 16 + k0];
        const float ak1 = Asm[g][i * 16 + k0 + 8];
        const float bj0 = Bsm[g][i * 16 + j0];
        const float bj1 = Bsm[g][i * 16 + j0 + 8];
        const float bk0 = Bsm[g][i * 16 + k0];
        const float bk1 = Bsm[g][i * 16 + k0 + 8];
        t00 += aj0 * bk0;  t01 += aj0 * bk1;  t10 += aj1 * bk0;  t11 += aj1 * bk1;
        p00 += aj0 * ak0;  p01 += aj0 * ak1;  p10 += aj1 * ak0;  p11 += aj1 * ak1;
        q00 += bj0 * bk0;  q01 += bj0 * bk1;  q10 += bj1 * bk0;  q11 += bj1 * bk1;
    }

    const float dr = rsqrtf(degrees[r] * (float)D_DIM + 1.0f);
    const float dc = rsqrtf(degrees[c] * (float)D_DIM + 1.0f);
    const float s  = -(dr * dc);
    const float sr = dr * dr;
    const float sc = dc * dc;

    // Diagonal Gram contributions straight into out's diag blocks
    float* dgr = &out[(size_t)(r * 16) * NM + r * 16];   // block (r,r), row stride NM
    atomicAdd(&dgr[(size_t)j0 * NM + k0],            sr * p00);
    atomicAdd(&dgr[(size_t)j0 * NM + k0 + 8],        sr * p01);
    atomicAdd(&dgr[(size_t)(j0 + 8) * NM + k0],      sr * p10);
    atomicAdd(&dgr[(size_t)(j0 + 8) * NM + k0 + 8],  sr * p11);

    float* dgc = &out[(size_t)(c * 16) * NM + c * 16];   // block (c,c)
    atomicAdd(&dgc[(size_t)j0 * NM + k0],            sc * q00);
    atomicAdd(&dgc[(size_t)j0 * NM + k0 + 8],        sc * q01);
    atomicAdd(&dgc[(size_t)(j0 + 8) * NM + k0],      sc * q10);
    atomicAdd(&dgc[(size_t)(j0 + 8) * NM + k0 + 8],  sc * q11);

    // Stage the scaled triu block in smem
    Tsm[g][j0][k0]          = s * t00;
    Tsm[g][j0][k0 + 8]      = s * t01;
    Tsm[g][j0 + 8][k0]      = s * t10;
    Tsm[g][j0 + 8][k0 + 8]  = s * t11;
    __syncthreads();

    // Re-map 64 threads to 16 rows x 4 float4 groups for coalesced stores
    const int j = lt >> 2;     // row 0..15
    const int q = lt & 3;      // float4 column group 0..3

    float4 v;                  // triu block, row j
    v.x = Tsm[g][j][q * 4 + 0];
    v.y = Tsm[g][j][q * 4 + 1];
    v.z = Tsm[g][j][q * 4 + 2];
    v.w = Tsm[g][j][q * 4 + 3];
    *(float4*)&out[(size_t)(r * 16 + j) * NM + c * 16 + q * 4] = v;

    float4 w;                  // tril block = transpose, row j
    w.x = Tsm[g][q * 4 + 0][j];
    w.y = Tsm[g][q * 4 + 1][j];
    w.z = Tsm[g][q * 4 + 2][j];
    w.w = Tsm[g][q * 4 + 3][j];
    *(float4*)&out[(size_t)(c * 16 + j) * NM + r * 16 + q * 4] = w;
}

extern "C" void kernel_launch(void* const* d_in, const int* in_sizes, int n_in,
                              void* d_out, int out_size) {
    // Inputs (metadata order): adj_mat [N*N f32], degrees [N f32],
    // maps [2E*16*16 f32], edge_index [2*2E int]
    const float* degrees = (const float*)d_in[1];
    const float* maps    = (const float*)d_in[2];
    const int*   eidx32  = (const int*)d_in[3];
    float*       out     = (float*)d_out;

    const int E = in_sizes[2] / (2 * 256);   // maps has 2E blocks of 256 floats

    // 1) Pure bandwidth-optimal zero fill of the 1.07 GB output (serial:
    //    measured 7.2 TB/s; any overlap degrades it — R5/R6 evidence)
    cudaMemsetAsync(d_out, 0, (size_t)out_size * sizeof(float), 0);

    // 2) Fused: compute + direct triu/tril stores + diag atomics into out
    edge_fused_kernel<<<E / 4, 256>>>(degrees, maps, eidx32, out, E);
}